// round 9
// baseline (speedup 1.0000x reference)
#include <cuda_runtime.h>
#include <cuda_fp16.h>
#include <cstdint>
#include <math.h>

static constexpr int Nd   = 8192;
static constexpr int Bd   = 256;
static constexpr int NNZc = 16 * Nd;
static constexpr int SLOTS = 64;          // padded CSR row capacity (max ~38 expected)

// ---------------- device scratch (no allocation) ----------------
__device__ __align__(1024) float  g_xt[Nd * Bd];        // x^T [N,B] fp32
__device__ __align__(1024) __half g_a0h[Bd * Nd];       // activations fp16 [B,N]
__device__ __align__(1024) __half g_h1h[Bd * Nd];
__device__ __align__(1024) __half g_h2h[Bd * Nd];
__device__ int   g_cnt[Nd];
__device__ __align__(1024) int2 g_cv[Nd * SLOTS];       // padded {col, val-bits}

// ---------------- helpers ----------------
__device__ __forceinline__ uint32_t smem_to_u32(const void* p) {
    uint32_t a;
    asm("{ .reg .u64 t; cvta.to.shared.u64 t, %1; cvt.u32.u64 %0, t; }" : "=r"(a) : "l"(p));
    return a;
}

__device__ __forceinline__ float selu_f(float x) {
    const float kS = 1.0507009873554805f;
    const float kA = 1.6732632423543772f;
    return x > 0.f ? kS * x : kS * kA * expm1f(x);
}

// A tile: 128 rows x 64 halves = 128B rows, SW128
__device__ __forceinline__ uint32_t swzA64(uint32_t r, uint32_t c) {
    uint32_t byte = r * 128u + c * 2u;
    return byte ^ ((byte >> 3) & 0x70u);
}
// B tile: 64 rows x 64 fp32 = 256B rows, SW128
__device__ __forceinline__ uint32_t swzB64(uint32_t r, uint32_t cw) {
    uint32_t byte = r * 256u + cw * 4u;
    return byte ^ ((byte >> 3) & 0x70u);
}

#define CP_ASYNC16(dst, src) \
    asm volatile("cp.async.cg.shared.global [%0], [%1], 16;" :: "r"(dst), "l"(src) : "memory")
#define CP_COMMIT() asm volatile("cp.async.commit_group;" ::: "memory")
#define CP_WAIT1()  asm volatile("cp.async.wait_group 1;" ::: "memory")

#define LDMATRIX_X4(r0, r1, r2, r3, addr) \
    asm volatile("ldmatrix.sync.aligned.m8n8.x4.shared.b16 {%0,%1,%2,%3}, [%4];" \
        : "=r"(r0), "=r"(r1), "=r"(r2), "=r"(r3) : "r"(addr))

#define MMA16816(d, a, b0, b1) \
    asm volatile("mma.sync.aligned.m16n8k16.row.col.f32.f16.f16.f32 " \
        "{%0,%1,%2,%3}, {%4,%5,%6,%7}, {%8,%9}, {%0,%1,%2,%3};" \
        : "+f"((d)[0]), "+f"((d)[1]), "+f"((d)[2]), "+f"((d)[3]) \
        : "r"((a)[0]), "r"((a)[1]), "r"((a)[2]), "r"((a)[3]), "r"(b0), "r"(b1))

// ---------------- sparse pipeline (3 launches) ----------------
__global__ void __launch_bounds__(256, 2) fused_prep_kernel(const float* __restrict__ x) {
    if (blockIdx.x < 2048) {
        __shared__ float t[32][33];
        int nb = (blockIdx.x & 255) * 32, bb = (blockIdx.x >> 8) * 32;
        int tx = threadIdx.x & 31, ty = threadIdx.x >> 5;
#pragma unroll
        for (int i = 0; i < 32; i += 8)
            t[ty + i][tx] = x[(size_t)(bb + ty + i) * Nd + nb + tx];
        __syncthreads();
#pragma unroll
        for (int i = 0; i < 32; i += 8)
            g_xt[(size_t)(nb + ty + i) * Bd + bb + tx] = t[tx][ty + i];
    } else {
#pragma unroll
        for (int i = 0; i < Nd / 256; i++) g_cnt[threadIdx.x + i * 256] = 0;
    }
}

__global__ void build_kernel(const int* __restrict__ rows, const int* __restrict__ cols,
                             const float* __restrict__ vals) {
    for (int i = blockIdx.x * blockDim.x + threadIdx.x; i < NNZc; i += gridDim.x * blockDim.x) {
        int r = rows[i];
        int p = atomicAdd(&g_cnt[r], 1);
        g_cv[r * SLOTS + p] = make_int2(cols[i], __float_as_int(vals[i]));
    }
}

__global__ void spmv_kernel(const float* __restrict__ bc, const float* __restrict__ flag) {
    int row = blockIdx.x * 8 + (threadIdx.x >> 5);
    int lane = threadIdx.x & 31;
    int n = g_cnt[row];
    const int2* cv = g_cv + row * SLOTS;
    float a0 = 0.f, a1 = 0.f, a2 = 0.f, a3 = 0.f, a4 = 0.f, a5 = 0.f, a6 = 0.f, a7 = 0.f;
    const float* xb = g_xt + lane * 8;
    if (n > 0) {
        int2 c0 = cv[0];
        for (int j = 0; j < n; j++) {
            int2 c1 = (j + 1 < n) ? cv[j + 1] : c0;
            float v = __int_as_float(c0.y);
            const float4* p = (const float4*)(xb + (size_t)c0.x * Bd);
            float4 u = p[0], w = p[1];
            a0 += v * u.x; a1 += v * u.y; a2 += v * u.z; a3 += v * u.w;
            a4 += v * w.x; a5 += v * w.y; a6 += v * w.z; a7 += v * w.w;
            c0 = c1;
        }
    }
    float bcv = bc[row], fl = flag[row];
    float r[8] = {a0, a1, a2, a3, a4, a5, a6, a7};
#pragma unroll
    for (int i = 0; i < 8; i++)
        g_a0h[(size_t)(lane * 8 + i) * Nd + row] = __float2half_rn(bcv + r[i] * fl);
}

// ---------------- fp16 mma.sync GEMM, CTA tile 128x64, 2 CTAs/SM ----------------
static constexpr int NSTAGE      = 3;
static constexpr int A_BYTES     = 16384;   // 128 x 64 halves
static constexpr int B_BYTES     = 16384;   // 64 x 64 fp32
static constexpr int STAGE_BYTES = A_BYTES + B_BYTES;       // 32 KB
static constexpr int GEMM_SMEM   = NSTAGE * STAGE_BYTES;    // 96 KB -> 2 CTAs/SM
static constexpr int KTILES      = Nd / 64; // 128

__device__ __forceinline__ void issue_stage(uint32_t sbase, int buf,
                                            const __half* At, const float* Wt,
                                            int k0, int tid) {
    uint32_t st = sbase + buf * STAGE_BYTES;
    // A: 1024 x 16B chunks (128B/row = 8 chunks)
#pragma unroll
    for (int i = 0; i < 4; i++) {
        int id = tid + i * 256;
        int r = id >> 3, ch = id & 7;
        const __half* src = At + (size_t)r * Nd + k0 + ch * 8;
        CP_ASYNC16(st + swzA64(r, ch * 8), src);
    }
    // B: 64 rows x 16 chunks = 1024 x 16B
#pragma unroll
    for (int i = 0; i < 4; i++) {
        int id = tid + i * 256;
        int r = id >> 4, ch = id & 15;
        const float* src = Wt + (size_t)r * Nd + k0 + ch * 4;
        CP_ASYNC16(st + A_BYTES + swzB64(r, ch * 4), src);
    }
}

struct Frags {
    uint32_t ar[4][4];
    uint32_t b0r[2], b1r[2];
};

__device__ __forceinline__ void load_frags(Frags& f, const char* smem,
                                           int stage, int ks, int wm, int wn, int lane) {
    uint32_t aOff = stage * STAGE_BYTES;
    uint32_t bOff = aOff + A_BYTES;
    uint32_t sb0 = smem_to_u32(smem);
    uint32_t acol = ks * 16 + (lane >> 4) * 8;
#pragma unroll
    for (int mf = 0; mf < 4; mf++) {
        uint32_t row = wm * 64 + mf * 16 + (lane & 15);
        LDMATRIX_X4(f.ar[mf][0], f.ar[mf][1], f.ar[mf][2], f.ar[mf][3],
                    sb0 + aOff + swzA64(row, acol));
    }
    uint32_t nrow = wn * 16 + (lane >> 2);
    uint32_t clo = ks * 16 + (lane & 3) * 2;
#pragma unroll
    for (int nf = 0; nf < 2; nf++) {
        uint32_t r = nrow + nf * 8;
        float2 lo = *(const float2*)(smem + bOff + swzB64(r, clo));
        float2 hi = *(const float2*)(smem + bOff + swzB64(r, clo + 8));
        __half2 h0 = __floats2half2_rn(lo.x, lo.y);
        __half2 h1 = __floats2half2_rn(hi.x, hi.y);
        f.b0r[nf] = *(uint32_t*)&h0;
        f.b1r[nf] = *(uint32_t*)&h1;
    }
}

__global__ void __launch_bounds__(256, 2)
gemm_f16_kernel(const __half* __restrict__ Ag, const float* __restrict__ Wg,
                const float* __restrict__ bias,
                const float* __restrict__ bc, const float* __restrict__ flag,
                void* __restrict__ outv, int mode)   // 0=selu->half, 1=addcmul->float
{
    extern __shared__ char smem[];
    uint32_t sb = smem_to_u32(smem);
    int tid = threadIdx.x, lane = tid & 31, w = tid >> 5;
    int wm = w & 1, wn = w >> 1;          // warp tile 64 x 16
    int mtile = blockIdx.x & 1, ntile = blockIdx.x >> 1;   // CTA tile 128 x 64

    const __half* At = Ag + (size_t)(mtile * 128) * Nd;
    const float*  Wt = Wg + (size_t)(ntile * 64) * Nd;

    float acc[4][2][4];
#pragma unroll
    for (int a = 0; a < 4; a++)
#pragma unroll
        for (int b = 0; b < 2; b++)
#pragma unroll
            for (int c = 0; c < 4; c++) acc[a][b][c] = 0.f;

#pragma unroll
    for (int s = 0; s < NSTAGE - 1; s++) {          // stages 0,1
        issue_stage(sb, s, At, Wt, s * 64, tid);
        CP_COMMIT();
    }

    Frags f0, f1;
#pragma unroll 1
    for (int t = 0; t < KTILES; t++) {
        // group g == stage g; wait 1 -> groups 0..t complete -> stage t ready
        CP_WAIT1();
        __syncthreads();     // stage t visible; stage t-1 reads all complete
        if (t + 2 < KTILES)
            issue_stage(sb, (t + 2) % NSTAGE, At, Wt, (t + 2) * 64, tid);
        CP_COMMIT();         // unconditional: exact group accounting

        int st = t % NSTAGE;
        load_frags(f0, smem, st, 0, wm, wn, lane);
#pragma unroll
        for (int ks = 0; ks < 4; ks++) {
            Frags& cur = (ks & 1) ? f1 : f0;
            Frags& nxt = (ks & 1) ? f0 : f1;
            if (ks < 3) load_frags(nxt, smem, st, ks + 1, wm, wn, lane);
#pragma unroll
            for (int mf = 0; mf < 4; mf++)
#pragma unroll
                for (int nf = 0; nf < 2; nf++)
                    MMA16816(acc[mf][nf], cur.ar[mf], cur.b0r[nf], cur.b1r[nf]);
        }
    }

#pragma unroll
    for (int mf = 0; mf < 4; mf++) {
#pragma unroll
        for (int nf = 0; nf < 2; nf++) {
            int r0 = mtile * 128 + wm * 64 + mf * 16 + (lane >> 2);
            int c0 = ntile * 64 + wn * 16 + nf * 8 + (lane & 3) * 2;
            float b0 = __ldg(&bias[c0]), b1 = __ldg(&bias[c0 + 1]);
            float v00 = acc[mf][nf][0] + b0, v01 = acc[mf][nf][1] + b1;
            float v10 = acc[mf][nf][2] + b0, v11 = acc[mf][nf][3] + b1;
            if (mode == 0) {
                __half2* o0 = (__half2*)((__half*)outv + (size_t)r0 * Nd + c0);
                __half2* o1 = (__half2*)((__half*)outv + (size_t)(r0 + 8) * Nd + c0);
                *o0 = __floats2half2_rn(selu_f(v00), selu_f(v01));
                *o1 = __floats2half2_rn(selu_f(v10), selu_f(v11));
            } else {
                float bc0 = __ldg(&bc[c0]), bc1 = __ldg(&bc[c0 + 1]);
                float fl0 = __ldg(&flag[c0]), fl1 = __ldg(&flag[c0 + 1]);
                float* o0 = (float*)outv + (size_t)r0 * Nd + c0;
                float* o1 = (float*)outv + (size_t)(r0 + 8) * Nd + c0;
                o0[0] = bc0 + v00 * fl0; o0[1] = bc1 + v01 * fl1;
                o1[0] = bc0 + v10 * fl0; o1[1] = bc1 + v11 * fl1;
            }
        }
    }
}

// ---------------- host ----------------
extern "C" void kernel_launch(void* const* d_in, const int* in_sizes, int n_in,
                              void* d_out, int out_size) {
    const float* x    = (const float*)d_in[0];
    const float* vals = (const float*)d_in[1];
    const float* bc   = (const float*)d_in[2];
    const float* flag = (const float*)d_in[3];
    const float* W1   = (const float*)d_in[4];
    const float* b1   = (const float*)d_in[5];
    const float* W2   = (const float*)d_in[6];
    const float* b2   = (const float*)d_in[7];
    const float* W3   = (const float*)d_in[8];
    const float* b3   = (const float*)d_in[9];
    const int*   rows = (const int*)d_in[10];
    const int*   cols = (const int*)d_in[11];

    void *pa0, *ph1, *ph2;
    cudaGetSymbolAddress(&pa0, g_a0h);
    cudaGetSymbolAddress(&ph1, g_h1h);
    cudaGetSymbolAddress(&ph2, g_h2h);

    cudaFuncSetAttribute(gemm_f16_kernel, cudaFuncAttributeMaxDynamicSharedMemorySize, GEMM_SMEM);

    fused_prep_kernel<<<2049, 256>>>(x);                                  // 0
    build_kernel<<<256, 256>>>(rows, cols, vals);                         // 1
    spmv_kernel<<<Nd / 8, 256>>>(bc, flag);                               // 2
    gemm_f16_kernel<<<256, 256, GEMM_SMEM>>>((__half*)pa0, W1, b1, bc, flag, ph1, 0);   // 3 <- ncu
    gemm_f16_kernel<<<256, 256, GEMM_SMEM>>>((__half*)ph1, W2, b2, bc, flag, ph2, 0);   // 4
    gemm_f16_kernel<<<256, 256, GEMM_SMEM>>>((__half*)ph2, W3, b3, bc, flag, d_out, 1); // 5
}